// round 1
// baseline (speedup 1.0000x reference)
#include <cuda_runtime.h>
#include <cstdint>

// Problem constants
#define ROWS_TOTAL 16384      // 4 * 4096 (batch * seq)
#define DIMK 4096             // inner dim
#define RR 8                  // LoRA rank
#define NL 3                  // number of LoRAs
#define LRTOT 24              // NL * RR
#define OUT_DIM 12288         // NL * 4096
#define LORA_OUT 4096

// -------- scratch (no allocations allowed) --------
__device__ float g_Apk[LRTOT * DIMK];        // A packed [lr][d] (lr-major)
__device__ float g_xa[ROWS_TOTAL * LRTOT];   // XA [row][lr]

// ============================================================
// k0: pack A0/A1/A2 ([dim][r] row-major) -> g_Apk [lr][d]
// ============================================================
__global__ void pack_A_kernel(const float* __restrict__ A0,
                              const float* __restrict__ A1,
                              const float* __restrict__ A2) {
    int idx = blockIdx.x * blockDim.x + threadIdx.x;   // over LRTOT*DIMK
    if (idx >= LRTOT * DIMK) return;
    int lr = idx / DIMK;
    int d  = idx % DIMK;
    int l  = lr >> 3;
    int r  = lr & 7;
    const float* A = (l == 0) ? A0 : (l == 1) ? A1 : A2;
    g_Apk[idx] = A[d * RR + r];
}

// ============================================================
// k1: XA = x @ Acat   ([16384 x 4096] @ [4096 x 24])
// Block: 256 threads, 128 rows. Thread tile: RT=4 rows x LT=3 lrs.
// tr = tid%32 (rows), tl = tid/32 (lr group, 8 groups x 3 = 24).
// smem x tile is d-major so the x read is 1 conflict-free LDS.128
// serving 4 rows; the A read is a warp-uniform broadcast.
// ============================================================
#define BROWS 128
#define DKC   64
#define RT    4
#define LT    3

__global__ __launch_bounds__(256, 1) void xa_kernel(const float* __restrict__ x) {
    __shared__ float xs[DKC][BROWS + 4];   // [d][row], padded
    __shared__ float as[DKC][LRTOT];       // [d][lr]

    int tid = threadIdx.x;
    int tr  = tid & 31;         // 0..31 -> rows tr*4 .. tr*4+3
    int tl  = tid >> 5;         // 0..7  -> lrs tl*3 .. tl*3+2
    int rowBase = blockIdx.x * BROWS;

    float acc[RT][LT];
#pragma unroll
    for (int i = 0; i < RT; i++)
#pragma unroll
        for (int j = 0; j < LT; j++) acc[i][j] = 0.0f;

    for (int dc = 0; dc < DIMK; dc += DKC) {
        // ---- stage x tile: BROWS x DKC floats (transpose to d-major) ----
#pragma unroll
        for (int it = 0; it < (BROWS * DKC / 4) / 256; it++) {
            int e   = tid + 256 * it;        // float4 index within tile
            int row = e / (DKC / 4);
            int d4  = e % (DKC / 4);
            float4 v = reinterpret_cast<const float4*>(
                x + (size_t)(rowBase + row) * DIMK + dc)[d4];
            xs[d4 * 4 + 0][row] = v.x;
            xs[d4 * 4 + 1][row] = v.y;
            xs[d4 * 4 + 2][row] = v.z;
            xs[d4 * 4 + 3][row] = v.w;
        }
        // ---- stage A tile: LRTOT x DKC floats (transpose to d-major) ----
        for (int e = tid; e < LRTOT * (DKC / 4); e += 256) {
            int lr = e / (DKC / 4);
            int d4 = e % (DKC / 4);
            float4 v = reinterpret_cast<const float4*>(
                g_Apk + lr * DIMK + dc)[d4];
            as[d4 * 4 + 0][lr] = v.x;
            as[d4 * 4 + 1][lr] = v.y;
            as[d4 * 4 + 2][lr] = v.z;
            as[d4 * 4 + 3][lr] = v.w;
        }
        __syncthreads();

#pragma unroll 16
        for (int d = 0; d < DKC; d++) {
            float4 xv = *reinterpret_cast<const float4*>(&xs[d][tr * 4]);
            float a0 = as[d][tl * 3 + 0];
            float a1 = as[d][tl * 3 + 1];
            float a2 = as[d][tl * 3 + 2];
            acc[0][0] += xv.x * a0;  acc[0][1] += xv.x * a1;  acc[0][2] += xv.x * a2;
            acc[1][0] += xv.y * a0;  acc[1][1] += xv.y * a1;  acc[1][2] += xv.y * a2;
            acc[2][0] += xv.z * a0;  acc[2][1] += xv.z * a1;  acc[2][2] += xv.z * a2;
            acc[3][0] += xv.w * a0;  acc[3][1] += xv.w * a1;  acc[3][2] += xv.w * a2;
        }
        __syncthreads();
    }

#pragma unroll
    for (int i = 0; i < RT; i++)
#pragma unroll
        for (int j = 0; j < LT; j++)
            g_xa[(size_t)(rowBase + tr * 4 + i) * LRTOT + tl * 3 + j] = acc[i][j];
}

// ============================================================
// k2: out = XA @ B (per lora), concatenated along last dim.
// Grid: (4 col tiles, 1024 row tiles, 3 loras). Block: 256 thr.
// Each block: 16 rows x 1024 cols of one lora. B rows held in
// registers (8 x float4), XA tile in smem (warp-uniform LDS),
// coalesced float4 stores.
// ============================================================
#define R2ROWS 16

__global__ __launch_bounds__(256, 1) void out_kernel(const float* __restrict__ B0,
                                                     const float* __restrict__ B1,
                                                     const float* __restrict__ B2,
                                                     float* __restrict__ out) {
    int l = blockIdx.z;
    const float* B = (l == 0) ? B0 : (l == 1) ? B1 : B2;
    int rowBase = blockIdx.y * R2ROWS;
    int o = blockIdx.x * 1024 + threadIdx.x * 4;   // column within this lora

    __shared__ float xa_s[R2ROWS][RR];
    if (threadIdx.x < R2ROWS * RR) {
        int i = threadIdx.x >> 3;
        int r = threadIdx.x & 7;
        xa_s[i][r] = g_xa[(size_t)(rowBase + i) * LRTOT + l * RR + r];
    }
    __syncthreads();

    float4 b[RR];
#pragma unroll
    for (int r = 0; r < RR; r++)
        b[r] = *reinterpret_cast<const float4*>(B + r * LORA_OUT + o);

#pragma unroll
    for (int i = 0; i < R2ROWS; i++) {
        float s0 = xa_s[i][0], s1 = xa_s[i][1], s2 = xa_s[i][2], s3 = xa_s[i][3];
        float s4 = xa_s[i][4], s5 = xa_s[i][5], s6 = xa_s[i][6], s7 = xa_s[i][7];
        float4 acc;
        acc.x = s0 * b[0].x; acc.y = s0 * b[0].y; acc.z = s0 * b[0].z; acc.w = s0 * b[0].w;
        acc.x += s1 * b[1].x; acc.y += s1 * b[1].y; acc.z += s1 * b[1].z; acc.w += s1 * b[1].w;
        acc.x += s2 * b[2].x; acc.y += s2 * b[2].y; acc.z += s2 * b[2].z; acc.w += s2 * b[2].w;
        acc.x += s3 * b[3].x; acc.y += s3 * b[3].y; acc.z += s3 * b[3].z; acc.w += s3 * b[3].w;
        acc.x += s4 * b[4].x; acc.y += s4 * b[4].y; acc.z += s4 * b[4].z; acc.w += s4 * b[4].w;
        acc.x += s5 * b[5].x; acc.y += s5 * b[5].y; acc.z += s5 * b[5].z; acc.w += s5 * b[5].w;
        acc.x += s6 * b[6].x; acc.y += s6 * b[6].y; acc.z += s6 * b[6].z; acc.w += s6 * b[6].w;
        acc.x += s7 * b[7].x; acc.y += s7 * b[7].y; acc.z += s7 * b[7].z; acc.w += s7 * b[7].w;

        size_t oidx = (size_t)(rowBase + i) * OUT_DIM + (size_t)l * LORA_OUT + o;
        *reinterpret_cast<float4*>(out + oidx) = acc;
    }
}

// ============================================================
// launch
// ============================================================
extern "C" void kernel_launch(void* const* d_in, const int* in_sizes, int n_in,
                              void* d_out, int out_size) {
    const float* x  = (const float*)d_in[0];
    const float* A0 = (const float*)d_in[1];
    const float* B0 = (const float*)d_in[2];
    const float* A1 = (const float*)d_in[3];
    const float* B1 = (const float*)d_in[4];
    const float* A2 = (const float*)d_in[5];
    const float* B2 = (const float*)d_in[6];
    float* out = (float*)d_out;

    // k0: pack A -> [24][4096]
    pack_A_kernel<<<(LRTOT * DIMK + 255) / 256, 256>>>(A0, A1, A2);

    // k1: XA (128 blocks, one full wave)
    xa_kernel<<<ROWS_TOTAL / BROWS, 256>>>(x);

    // k2: out (4 col tiles x 1024 row tiles x 3 loras)
    dim3 grid2(LORA_OUT / 1024, ROWS_TOTAL / R2ROWS, NL);
    out_kernel<<<grid2, 256>>>(B0, B1, B2, out);
}

// round 4
// speedup vs baseline: 1.6624x; 1.6624x over previous
#include <cuda_runtime.h>
#include <cstdint>

// Problem constants
#define ROWS_TOTAL 16384      // 4 * 4096 (batch * seq)
#define DIMK 4096             // inner dim
#define RR 8                  // LoRA rank
#define NL 3                  // number of LoRAs
#define LRTOT 24              // NL * RR
#define OUT_DIM 12288         // NL * 4096
#define LORA_OUT 4096

#define NXA (ROWS_TOTAL * LRTOT)   // 393216

typedef unsigned long long ull;

// -------- scratch (no allocations allowed) --------
__device__ float  g_Apk[LRTOT * DIMK];     // A packed [lr][d]
__device__ float  g_xap[4 * NXA];          // XA partials per k-slice
__device__ float2 g_xa2[NXA];              // XA final, duplicated (s,s)

__device__ __forceinline__ void ffma2(ull& acc, ull a, ull b) {
    asm("fma.rn.f32x2 %0, %1, %2, %0;" : "+l"(acc) : "l"(a), "l"(b));
}

// ============================================================
// k0: pack A0/A1/A2 ([dim][r] row-major) -> g_Apk [lr][d]
// ============================================================
__global__ void pack_A_kernel(const float* __restrict__ A0,
                              const float* __restrict__ A1,
                              const float* __restrict__ A2) {
    int idx = blockIdx.x * blockDim.x + threadIdx.x;   // over LRTOT*DIMK
    if (idx >= LRTOT * DIMK) return;
    int lr = idx / DIMK;
    int d  = idx % DIMK;
    int l  = lr >> 3;
    int r  = lr & 7;
    const float* A = (l == 0) ? A0 : (l == 1) ? A1 : A2;
    g_Apk[idx] = A[d * RR + r];
}

// ============================================================
// k1: XA = x @ Acat, split-K x4.
// Block: 128 threads, 128 rows, 1024-d slice.
// Thread tile: 4 rows (rg, rg+32, rg+64, rg+96) x 6 lr.
// f32x2: accumulator halves = even-d / odd-d partial sums.
// x staged d-packed: xs4[d4][row] = float4 of 4 consecutive d.
// A staged as d-pairs: as2[d2][lr] = (a[2k], a[2k+1]).
// ============================================================
#define DKC 32          // d per chunk
#define KS  4           // k slices
#define XPAD 131        // row-dim stride of xs4 (float4 units)

__global__ __launch_bounds__(128, 4) void xa_kernel(const float* __restrict__ x) {
    __shared__ float4 xs4[DKC / 4][XPAD];      // [d4][row] (rows 0..127)
    __shared__ float2 as2[DKC / 2][LRTOT];     // [d-pair][lr]

    int tid = threadIdx.x;
    int rg  = tid & 31;          // row group: rows rg + 32*i
    int lg  = tid >> 5;          // lr group: lr  lg*6 + j
    int rowBase = blockIdx.x * 128;
    int dBase   = blockIdx.y * (DIMK / KS);

    ull acc[4][6];
#pragma unroll
    for (int i = 0; i < 4; i++)
#pragma unroll
        for (int j = 0; j < 6; j++) acc[i][j] = 0ull;

    for (int dc = 0; dc < DIMK / KS; dc += DKC) {
        // ---- stage x: 128 rows x 32 d = 1024 float4, 8 per thread ----
#pragma unroll
        for (int it = 0; it < 8; it++) {
            int e   = tid + 128 * it;
            int row = e >> 3;
            int d4  = e & 7;
            float4 v = reinterpret_cast<const float4*>(
                x + (size_t)(rowBase + row) * DIMK + dBase + dc)[d4];
            xs4[d4][row] = v;
        }
        // ---- stage A pairs: 16 d2 x 24 lr = 384 float2, 3 per thread ----
#pragma unroll
        for (int it = 0; it < 3; it++) {
            int e  = tid + 128 * it;
            int lr = e >> 4;
            int d2 = e & 15;
            as2[d2][lr] = *reinterpret_cast<const float2*>(
                g_Apk + lr * DIMK + dBase + dc + 2 * d2);
        }
        __syncthreads();

#pragma unroll 8
        for (int dp = 0; dp < DKC / 2; dp++) {
            int d4   = dp >> 1;
            int half = dp & 1;
            // x pairs: 4 rows
            ull xp[4];
#pragma unroll
            for (int i = 0; i < 4; i++) {
                const float4* p = &xs4[d4][rg + 32 * i];
                xp[i] = *reinterpret_cast<const ull*>(
                    reinterpret_cast<const char*>(p) + 8 * half);
            }
            // a pairs: 6 lr via 3x 16B loads (warp-uniform)
            ull ap[6];
#pragma unroll
            for (int q = 0; q < 3; q++) {
                ulonglong2 t = *reinterpret_cast<const ulonglong2*>(&as2[dp][lg * 6 + 2 * q]);
                ap[2 * q]     = t.x;
                ap[2 * q + 1] = t.y;
            }
#pragma unroll
            for (int i = 0; i < 4; i++)
#pragma unroll
                for (int j = 0; j < 6; j++)
                    ffma2(acc[i][j], xp[i], ap[j]);
        }
        __syncthreads();
    }

    // write partials: sum even/odd halves
#pragma unroll
    for (int i = 0; i < 4; i++)
#pragma unroll
        for (int j = 0; j < 6; j++) {
            float2 v = *reinterpret_cast<float2*>(&acc[i][j]);
            int row = rowBase + rg + 32 * i;
            g_xap[blockIdx.y * NXA + (size_t)row * LRTOT + lg * 6 + j] = v.x + v.y;
        }
}

// ============================================================
// k1b: reduce k-slices and duplicate -> g_xa2[(row,lr)] = (s,s)
// ============================================================
__global__ void reduce_xa_kernel() {
    int idx = blockIdx.x * blockDim.x + threadIdx.x;
    if (idx >= NXA) return;
    float s = g_xap[idx] + g_xap[NXA + idx] + g_xap[2 * NXA + idx] + g_xap[3 * NXA + idx];
    g_xa2[idx] = make_float2(s, s);
}

// ============================================================
// k2: out = XA @ B (per lora), f32x2.
// Grid: (4 col tiles, 512 row tiles, 3 loras). Block: 256 thr.
// Each block: 32 rows x 1024 cols of one lora.
// B rows in registers as f32x2 pairs; s broadcast as (s,s) from smem.
// ============================================================
#define R2ROWS 32

__global__ __launch_bounds__(256, 4) void out_kernel(const float* __restrict__ B0,
                                                     const float* __restrict__ B1,
                                                     const float* __restrict__ B2,
                                                     float* __restrict__ out) {
    int l = blockIdx.z;
    const float* B = (l == 0) ? B0 : (l == 1) ? B1 : B2;
    int rowBase = blockIdx.y * R2ROWS;
    int o = blockIdx.x * 1024 + threadIdx.x * 4;   // column within this lora

    __shared__ float2 xa_s[R2ROWS][RR];            // duplicated (s,s)
    {
        int i = threadIdx.x >> 3;
        int r = threadIdx.x & 7;
        xa_s[i][r] = g_xa2[(size_t)(rowBase + i) * LRTOT + l * RR + r];
    }
    __syncthreads();

    // B columns o..o+3 for all 8 r, as f32x2 pairs
    ull blo[RR], bhi[RR];
#pragma unroll
    for (int r = 0; r < RR; r++) {
        float4 b = *reinterpret_cast<const float4*>(B + r * LORA_OUT + o);
        ulonglong2 u = *reinterpret_cast<ulonglong2*>(&b);
        blo[r] = u.x;
        bhi[r] = u.y;
    }

#pragma unroll 4
    for (int i = 0; i < R2ROWS; i++) {
        ull s[RR];
#pragma unroll
        for (int r = 0; r < RR; r++)
            s[r] = *reinterpret_cast<const ull*>(&xa_s[i][r]);   // broadcast

        ull a0 = 0ull, a1 = 0ull;
#pragma unroll
        for (int r = 0; r < RR; r++) {
            ffma2(a0, s[r], blo[r]);
            ffma2(a1, s[r], bhi[r]);
        }
        float4 res;
        *reinterpret_cast<ull*>(&res.x) = a0;
        *reinterpret_cast<ull*>(&res.z) = a1;

        size_t oidx = (size_t)(rowBase + i) * OUT_DIM + (size_t)l * LORA_OUT + o;
        __stcs(reinterpret_cast<float4*>(out + oidx), res);
    }
}

// ============================================================
// launch
// ============================================================
extern "C" void kernel_launch(void* const* d_in, const int* in_sizes, int n_in,
                              void* d_out, int out_size) {
    const float* x  = (const float*)d_in[0];
    const float* A0 = (const float*)d_in[1];
    const float* B0 = (const float*)d_in[2];
    const float* A1 = (const float*)d_in[3];
    const float* B1 = (const float*)d_in[4];
    const float* A2 = (const float*)d_in[5];
    const float* B2 = (const float*)d_in[6];
    float* out = (float*)d_out;

    pack_A_kernel<<<(LRTOT * DIMK + 255) / 256, 256>>>(A0, A1, A2);

    dim3 grid1(ROWS_TOTAL / 128, KS);          // 128 x 4 = 512 blocks
    xa_kernel<<<grid1, 128>>>(x);

    reduce_xa_kernel<<<(NXA + 255) / 256, 256>>>();

    dim3 grid2(LORA_OUT / 1024, ROWS_TOTAL / R2ROWS, NL);  // 4 x 512 x 3
    out_kernel<<<grid2, 256>>>(B0, B1, B2, out);
}